// round 4
// baseline (speedup 1.0000x reference)
#include <cuda_runtime.h>
#include <cstdint>

// Per-row top-k masking (keep k largest/smallest along last axis, zero the rest).
// One warp per row of C=768 floats. Register-lean version: only packed top-bytes
// persist in registers; x is re-read from L1 for candidate extraction and the
// final threshold pass (per-CTA 24KB working set stays L1/L2 resident).

#define FULL_MASK 0xFFFFFFFFu

constexpr int C_DIM  = 768;
constexpr int V4     = 6;     // float4 loads per thread
constexpr int WARPS  = 8;     // rows per block
constexpr int CAP    = 256;   // candidate slots per warp (smem)

__device__ __forceinline__ unsigned f2ord(unsigned b) {
    return b ^ (unsigned)(((int)b >> 31) | 0x80000000);
}
__device__ __forceinline__ unsigned ord2f(unsigned u) {
    return u ^ (unsigned)(0x80000000u | ~((unsigned)((int)u >> 31)));
}

// Sort <=32 values (ascending) across the warp, return the r-th largest (1-based).
__device__ __forceinline__ unsigned warp_rank_select(const unsigned* cand,
                                                     int m, int r, int lane)
{
    unsigned v = (lane < m) ? cand[lane] : 0u;
    #pragma unroll
    for (int size = 2; size <= 32; size <<= 1) {
        #pragma unroll
        for (int stride = size >> 1; stride > 0; stride >>= 1) {
            unsigned o = __shfl_xor_sync(FULL_MASK, v, stride);
            bool tm = (((lane & stride) != 0) ^ ((lane & size) != 0));
            unsigned mx = v > o ? v : o;
            unsigned mn = v > o ? o : v;
            v = tm ? mx : mn;
        }
    }
    return __shfl_sync(FULL_MASK, v, 32 - r);
}

__global__ __launch_bounds__(WARPS * 32, 6)
void topk_mask_kernel(const float* __restrict__ x,
                      const int* __restrict__ kptr,
                      const int* __restrict__ lptr,
                      float* __restrict__ out,
                      int nrows)
{
    __shared__ unsigned s_cand[WARPS][CAP];

    const int warp = threadIdx.x >> 5;
    const int lane = threadIdx.x & 31;
    const int row  = blockIdx.x * WARPS + warp;
    if (row >= nrows) return;

    const int k       = *kptr;
    const int largest = *lptr;
    const unsigned flip = largest ? 0u : 0xFFFFFFFFu;

    const float4* __restrict__ xin =
        reinterpret_cast<const float4*>(x + (size_t)row * C_DIM);
    float4* __restrict__ xout =
        reinterpret_cast<float4*>(out + (size_t)row * C_DIM);

    const unsigned H  = 0x80808080u;
    const unsigned NH = 0x7F7F7F7Fu;
    const unsigned HX = H ^ flip;

    // ---- pass A: load + pack ordered top-bytes into 6 words (f not kept) ----
    unsigned p[V4], xm[V4];
    #pragma unroll
    for (int j = 0; j < V4; j++) {
        float4 v = xin[lane + 32 * j];
        unsigned p01 = __byte_perm(__float_as_uint(v.x), __float_as_uint(v.y), 0x0073);
        unsigned p23 = __byte_perm(__float_as_uint(v.z), __float_as_uint(v.w), 0x0073);
        unsigned pk  = __byte_perm(p01, p23, 0x5410);
        unsigned s   = pk & H;
        unsigned mm  = (s >> 7) * 0x7Fu;
        p[j]  = pk ^ mm ^ HX;
        xm[j] = p[j] & NH;
    }

    // ---- 8-step binary search on the top byte (dp4a-accumulated counts) ----
    unsigned lo = 0, hi = 256;
    int flo = C_DIM, fhi = 0;
    #pragma unroll
    for (int it = 0; it < 8; it++) {
        unsigned mid  = (lo + hi) >> 1;              // in [1,255]
        unsigned crep = (256u - mid) * 0x01010101u;
        unsigned cqm  = crep & NH;
        unsigned acc  = 0;
        #pragma unroll
        for (int j = 0; j < V4; j++) {
            unsigned s = xm[j] + cqm;                          // carries into bit7
            unsigned g = (p[j] & crep) | ((p[j] ^ crep) & s);  // single LOP3
            acc = __dp4a(g & H, 0x01010101u, acc);             // += 0x80 per match
        }
        int cnt = __reduce_add_sync(FULL_MASK, (int)acc) >> 7;
        if (cnt >= k) { lo = mid; flo = cnt; }
        else          { hi = mid; fhi = cnt; }
    }
    const unsigned d = lo;
    int r = k - fhi;           // rank of k-th value inside the d-bin (1-based)
    int m = flo - fhi;         // bin population

    // ---- per-byte equality masks + scan, then re-read x to emit candidates ----
    const unsigned drep = d * 0x01010101u;
    const unsigned dr7  = drep & NH;
    unsigned ym[V4];
    int ci = 0;
    #pragma unroll
    for (int j = 0; j < V4; j++) {
        unsigned z = p[j] ^ drep;
        unsigned a = (xm[j] ^ dr7) + NH;         // no cross-byte carry
        unsigned y = ~(a | z) & H;               // 0x80 per byte equal to d
        ym[j] = y;
        ci += __popc(y);
    }
    int sc = ci;
    #pragma unroll
    for (int sh = 1; sh < 32; sh <<= 1) {
        int t = __shfl_up_sync(FULL_MASK, sc, sh);
        if (lane >= sh) sc += t;
    }
    unsigned* cand = s_cand[warp];
    if (m <= CAP) {
        int pos = sc - ci;                       // exclusive prefix
        #pragma unroll
        for (int j = 0; j < V4; j++) {
            if (ym[j]) {
                float4 v = xin[lane + 32 * j];   // L1 hit
                unsigned w[4] = { __float_as_uint(v.x), __float_as_uint(v.y),
                                  __float_as_uint(v.z), __float_as_uint(v.w) };
                #pragma unroll
                for (int b = 0; b < 4; b++) {
                    if (ym[j] & (0x80u << (8*b)))
                        cand[pos++] = f2ord(w[b]) ^ flip;
                }
            }
        }
    }
    __syncwarp();

    // ---- rank-select the r-th largest among the m candidates ----
    unsigned cur = d << 24;
    unsigned thr_ord;

    if (m <= 32) {
        thr_ord = warp_rank_select(cand, m, r, lane);
    } else if (m <= 128) {
        int bse = 0;
        int bi  = 2;
        while (m > 32 && bi >= 0) {
            const int W = (m + 31) >> 5;         // <= 4
            int cb[4];
            #pragma unroll
            for (int j = 0; j < 4; j++) {
                int idx = lane + 32 * j;
                cb[j] = (j < W && idx < m)
                      ? (int)((cand[bse + idx] >> (8*bi)) & 0xFFu) : -1;
            }
            unsigned lo2 = 0, hi2 = 256;
            int flo2 = m, fhi2 = 0;
            #pragma unroll
            for (int it = 0; it < 8; it++) {
                int mid = (int)((lo2 + hi2) >> 1);
                int c = 0;
                #pragma unroll
                for (int j = 0; j < 4; j++) c += (cb[j] >= mid) ? 1 : 0;
                c = __reduce_add_sync(FULL_MASK, c);
                if (c >= r) { lo2 = mid; flo2 = c; }
                else        { hi2 = mid; fhi2 = c; }
            }
            const int d2 = (int)lo2;
            const int m2 = flo2 - fhi2;
            r  -= fhi2;
            cur |= ((unsigned)d2) << (8*bi);
            // compact survivors into the other half (m<=128: halves disjoint)
            int fl[4]; int c2 = 0;
            #pragma unroll
            for (int j = 0; j < 4; j++) { fl[j] = (cb[j] == d2); c2 += fl[j]; }
            int s2 = c2;
            #pragma unroll
            for (int sh = 1; sh < 32; sh <<= 1) {
                int t = __shfl_up_sync(FULL_MASK, s2, sh);
                if (lane >= sh) s2 += t;
            }
            int pos = ((bse == 0) ? 128 : 0) + (s2 - c2);
            #pragma unroll
            for (int j = 0; j < 4; j++) {
                if (fl[j]) cand[pos++] = cand[bse + lane + 32*j];
            }
            __syncwarp();
            bse = (bse == 0) ? 128 : 0;
            m = m2; bi--;
        }
        if (m <= 32) thr_ord = warp_rank_select(cand + bse, m, r, lane);
        else         thr_ord = cur;              // all bytes fixed: all equal
    } else if (m <= CAP) {
        // heavy bin: exact strided bit-loop over smem candidates
        const bool valid0 = (lane < m);
        const unsigned v0 = valid0 ? cand[lane] : 0u;
        #pragma unroll 1
        for (int b = 23; b >= 0; b--) {
            int cl = (valid0 && (((v0 ^ cur) >> b) == 1u)) ? 1 : 0;
            for (int j = 32 + lane; j < m; j += 32)
                cl += (((cand[j] ^ cur) >> b) == 1u) ? 1 : 0;
            int c = __reduce_add_sync(FULL_MASK, cl);
            if (c >= r) cur |= (1u << b);
            else        r -= c;
        }
        thr_ord = cur;
    } else {
        // pathological bin (> CAP candidates): exact bit-loop over global re-reads
        #pragma unroll 1
        for (int b = 23; b >= 0; b--) {
            int cl = 0;
            #pragma unroll
            for (int j = 0; j < V4; j++) {
                float4 v = xin[lane + 32 * j];
                unsigned w[4] = { __float_as_uint(v.x), __float_as_uint(v.y),
                                  __float_as_uint(v.z), __float_as_uint(v.w) };
                #pragma unroll
                for (int b4 = 0; b4 < 4; b4++) {
                    unsigned uu = f2ord(w[b4]) ^ flip;
                    cl += (((uu ^ cur) >> b) == 1u) ? 1 : 0;
                }
            }
            int c = __reduce_add_sync(FULL_MASK, cl);
            if (c >= r) cur |= (1u << b);
            else        r -= c;
        }
        thr_ord = cur;
    }

    // ---- pass C: re-read x (L1) and write thresholded output ----
    if (largest) {
        const float thr = __uint_as_float(ord2f(thr_ord));
        #pragma unroll
        for (int i = 0; i < V4; i++) {
            float4 v = xin[lane + 32 * i];
            float4 o;
            o.x = (v.x >= thr) ? v.x : 0.0f;
            o.y = (v.y >= thr) ? v.y : 0.0f;
            o.z = (v.z >= thr) ? v.z : 0.0f;
            o.w = (v.w >= thr) ? v.w : 0.0f;
            xout[lane + 32 * i] = o;
        }
    } else {
        const float thr = __uint_as_float(ord2f(thr_ord ^ flip));
        #pragma unroll
        for (int i = 0; i < V4; i++) {
            float4 v = xin[lane + 32 * i];
            float4 o;
            o.x = (v.x <= thr) ? v.x : 0.0f;
            o.y = (v.y <= thr) ? v.y : 0.0f;
            o.z = (v.z <= thr) ? v.z : 0.0f;
            o.w = (v.w <= thr) ? v.w : 0.0f;
            xout[lane + 32 * i] = o;
        }
    }
}

extern "C" void kernel_launch(void* const* d_in, const int* in_sizes, int n_in,
                              void* d_out, int out_size)
{
    const float* x    = (const float*)d_in[0];
    const int*   kptr = (const int*)d_in[1];
    const int*   lptr = (const int*)d_in[2];
    float* out = (float*)d_out;

    int nrows = in_sizes[0] / C_DIM;
    int blocks = (nrows + WARPS - 1) / WARPS;
    topk_mask_kernel<<<blocks, WARPS * 32>>>(x, kptr, lptr, out, nrows);
}